// round 4
// baseline (speedup 1.0000x reference)
#include <cuda_runtime.h>

// LELoss: loss = S1/B + 1.1*S2/B + 0.1*S3/400
//   S1 = sum (x - decoded)^2              over [8192,1024]
//   S2 = sum (encoded - latent@rsrA^T)^2  over [8192,128], I=20
//   S3 = sum (rsrA^T rsrA - I)^2          over [20,20], E=128
// kNN/top_k in the reference is dead code (result unused).
// Single fused kernel; last block (threadfence pattern) finishes the scalar.
// __launch_bounds__(256,4) caps regs at 64 so 4 CTAs/SM fit (R2 lesson:
// 116 regs -> 2 CTAs/SM -> latency-bound -> 35us).

#define B_DIM   8192
#define D_DIM   1024
#define E_DIM   128
#define I_DIM   20
#define THREADS 256
#define NBLK    592          // 4 CTAs per SM on 148 SMs

#define N4_A    ((B_DIM * D_DIM) / 4)   // 2,097,152 float4 pairs
#define N4_B    ((B_DIM * E_DIM) / 4)   // 262,144 float4 of encoded

__device__ double        g_partials[NBLK];
__device__ unsigned int  g_count = 0;    // atomicInc wraps to 0 -> replay-safe

__global__ __launch_bounds__(THREADS, 4) void loss_fused_kernel(
    const float* __restrict__ x,
    const float* __restrict__ encoded,
    const float* __restrict__ latent,
    const float* __restrict__ decoded,
    const float* __restrict__ rsrA,
    float* __restrict__ out)
{
    __shared__ float rs[I_DIM * E_DIM];   // rsrA transposed: rs[i*128 + e]

    const int tid    = threadIdx.x;
    const int g      = blockIdx.x * THREADS + tid;
    const int stride = NBLK * THREADS;

    // Stage rsrA transposed into shared (10 KB)
    for (int j = tid; j < I_DIM * E_DIM; j += THREADS) {
        int i = j >> 7;          // j / 128
        int e = j & (E_DIM - 1); // j % 128
        rs[j] = rsrA[e * I_DIM + i];
    }

    // ---- Part A: S1 = sum (x - decoded)^2, float4, 4-way unrolled ----
    const float4* __restrict__ x4 = (const float4*)x;
    const float4* __restrict__ d4 = (const float4*)decoded;

    float s1 = 0.0f;
    int i = g;
    for (; i + 3 * stride < N4_A; i += 4 * stride) {
        float4 a0 = x4[i];
        float4 a1 = x4[i + stride];
        float4 a2 = x4[i + 2 * stride];
        float4 a3 = x4[i + 3 * stride];
        float4 b0 = d4[i];
        float4 b1 = d4[i + stride];
        float4 b2 = d4[i + 2 * stride];
        float4 b3 = d4[i + 3 * stride];
        float t;
        t = a0.x - b0.x; s1 += t * t;  t = a0.y - b0.y; s1 += t * t;
        t = a0.z - b0.z; s1 += t * t;  t = a0.w - b0.w; s1 += t * t;
        t = a1.x - b1.x; s1 += t * t;  t = a1.y - b1.y; s1 += t * t;
        t = a1.z - b1.z; s1 += t * t;  t = a1.w - b1.w; s1 += t * t;
        t = a2.x - b2.x; s1 += t * t;  t = a2.y - b2.y; s1 += t * t;
        t = a2.z - b2.z; s1 += t * t;  t = a2.w - b2.w; s1 += t * t;
        t = a3.x - b3.x; s1 += t * t;  t = a3.y - b3.y; s1 += t * t;
        t = a3.z - b3.z; s1 += t * t;  t = a3.w - b3.w; s1 += t * t;
    }
    for (; i < N4_A; i += stride) {
        float4 a = x4[i];
        float4 b = d4[i];
        float t;
        t = a.x - b.x; s1 += t * t;  t = a.y - b.y; s1 += t * t;
        t = a.z - b.z; s1 += t * t;  t = a.w - b.w; s1 += t * t;
    }

    __syncthreads();   // rs ready

    // ---- Part B: S2 = sum (encoded - latent @ rsrA^T)^2 ----
    const float4* __restrict__ enc4 = (const float4*)encoded;
    float s2 = 0.0f;
    for (int idx = g; idx < N4_B; idx += stride) {
        int b  = idx >> 5;           // 32 float4 per row
        int e  = (idx & 31) << 2;    // base e column
        const float* __restrict__ lrow = latent + b * I_DIM;
        float4 enc = enc4[idx];
        float a0 = -enc.x, a1 = -enc.y, a2 = -enc.z, a3 = -enc.w;
        #pragma unroll
        for (int k = 0; k < I_DIM; k++) {
            float l = lrow[k];                 // warp-broadcast, L1 hit
            const float* r = &rs[k * E_DIM + e];
            a0 += l * r[0];
            a1 += l * r[1];
            a2 += l * r[2];
            a3 += l * r[3];
        }
        s2 += a0 * a0 + a1 * a1 + a2 * a2 + a3 * a3;
    }

    // ---- Block reduction (deterministic tree), partial = s1 + 1.1*s2 ----
    __shared__ float red[THREADS];
    red[tid] = s1 + 1.1f * s2;
    __syncthreads();
    #pragma unroll
    for (int off = THREADS / 2; off > 0; off >>= 1) {
        if (tid < off) red[tid] += red[tid + off];
        __syncthreads();
    }

    // ---- Last-block final reduction (threadfence pattern) ----
    __shared__ bool is_last;
    if (tid == 0) {
        g_partials[blockIdx.x] = (double)red[0];
        __threadfence();
        // atomicInc wraps old==NBLK-1 -> 0: counter self-resets every launch
        unsigned int prev = atomicInc(&g_count, NBLK - 1);
        is_last = (prev == NBLK - 1);
    }
    __syncthreads();

    if (is_last) {
        __shared__ double sdd[THREADS];
        __shared__ float  sff[THREADS];

        // Sum all block partials in fixed per-thread order -> deterministic
        double sum = 0.0;
        for (int j = tid; j < NBLK; j += THREADS) sum += g_partials[j];
        sdd[tid] = sum;

        // S3: Gram residual, 400 (p,q) pairs, dot over E=128 (from shared rs)
        float s3 = 0.0f;
        for (int pq = tid; pq < I_DIM * I_DIM; pq += THREADS) {
            int p = pq / I_DIM;
            int q = pq - p * I_DIM;
            const float* rp = &rs[p * E_DIM];
            const float* rq = &rs[q * E_DIM];
            float gacc = 0.0f;
            #pragma unroll 4
            for (int e = 0; e < E_DIM; e++)
                gacc += rp[e] * rq[e];
            if (p == q) gacc -= 1.0f;
            s3 += gacc * gacc;
        }
        sff[tid] = s3;
        __syncthreads();

        #pragma unroll
        for (int off = THREADS / 2; off > 0; off >>= 1) {
            if (tid < off) {
                sdd[tid] += sdd[tid + off];
                sff[tid] += sff[tid + off];
            }
            __syncthreads();
        }

        if (tid == 0) {
            double total = sdd[0] / (double)B_DIM
                         + 0.1 * (double)sff[0] / (double)(I_DIM * I_DIM);
            out[0] = (float)total;
        }
    }
}

extern "C" void kernel_launch(void* const* d_in, const int* in_sizes, int n_in,
                              void* d_out, int out_size) {
    const float* x       = (const float*)d_in[0];
    const float* encoded = (const float*)d_in[1];
    const float* latent  = (const float*)d_in[2];
    const float* decoded = (const float*)d_in[3];
    const float* rsrA    = (const float*)d_in[4];
    float* out = (float*)d_out;

    loss_fused_kernel<<<NBLK, THREADS>>>(x, encoded, latent, decoded, rsrA, out);
}

// round 5
// speedup vs baseline: 1.2088x; 1.2088x over previous
#include <cuda_runtime.h>

// LELoss: loss = S1/B + 1.1*S2/B + 0.1*S3/400
//   S1 = sum (x - decoded)^2              over [8192,1024]
//   S2 = sum (encoded - latent@rsrA^T)^2  over [8192,128], I=20
//   S3 = sum (rsrA^T rsrA - I)^2          over [20,20], E=128
// kNN/top_k in the reference is dead code (result unused).
//
// R5: the body is fp32-ISSUE-bound (~38M scalar fp32 instr), not HBM-bound.
// Use packed f32x2 (fma.rn.f32x2 / mul.rn.f32x2, sm_103a) to halve the
// fp32 instruction count. float4 data is loaded as ulonglong2 so each
// 64-bit register already holds a packed f32x2 pair (no pack cost).
// Two kernels (fusion bloated regs / spilled in R2/R4).

#define B_DIM   8192
#define D_DIM   1024
#define E_DIM   128
#define I_DIM   20
#define THREADS 256
#define NBLK    592          // 4 CTAs per SM on 148 SMs

#define N4_A    ((B_DIM * D_DIM) / 4)   // 2,097,152 float4 pairs
#define N4_B    ((B_DIM * E_DIM) / 4)   // 262,144 float4 of encoded

typedef unsigned long long u64;

__device__ double g_partials[NBLK];

__device__ __forceinline__ u64 fma2(u64 a, u64 b, u64 c) {
    u64 d;
    asm("fma.rn.f32x2 %0, %1, %2, %3;" : "=l"(d) : "l"(a), "l"(b), "l"(c));
    return d;
}
__device__ __forceinline__ u64 mul2(u64 a, u64 b) {
    u64 d;
    asm("mul.rn.f32x2 %0, %1, %2;" : "=l"(d) : "l"(a), "l"(b));
    return d;
}
__device__ __forceinline__ u64 pack2(float lo, float hi) {
    u64 r;
    asm("mov.b64 %0, {%1, %2};" : "=l"(r) : "f"(lo), "f"(hi));
    return r;
}
__device__ __forceinline__ float2 unpack2(u64 v) {
    float lo, hi;
    asm("mov.b64 {%0, %1}, %2;" : "=f"(lo), "=f"(hi) : "l"(v));
    return make_float2(lo, hi);
}

__global__ __launch_bounds__(THREADS, 4) void loss_main_kernel(
    const float* __restrict__ x,
    const float* __restrict__ encoded,
    const float* __restrict__ latent,
    const float* __restrict__ decoded,
    const float* __restrict__ rsrA)
{
    __shared__ float rs[I_DIM * E_DIM];   // rsrA transposed: rs[i*128 + e]

    const int tid    = threadIdx.x;
    const int g      = blockIdx.x * THREADS + tid;
    const int stride = NBLK * THREADS;

    // Stage rsrA transposed into shared (10 KB)
    for (int j = tid; j < I_DIM * E_DIM; j += THREADS) {
        int i = j >> 7;          // j / 128
        int e = j & (E_DIM - 1); // j % 128
        rs[j] = rsrA[e * I_DIM + i];
    }

    const u64 neg1 = pack2(-1.0f, -1.0f);

    // ---- Part A: S1 = sum (x - decoded)^2, f32x2 packed, 4-way unrolled ----
    // diff = fma2(b, -1, a); acc = fma2(diff, diff, acc)  -> 1 instr per elem
    const ulonglong2* __restrict__ x8 = (const ulonglong2*)x;
    const ulonglong2* __restrict__ d8 = (const ulonglong2*)decoded;

    u64 accA = 0ull, accB = 0ull;   // 0x0 == {0.f, 0.f}
    int i = g;
    for (; i + 3 * stride < N4_A; i += 4 * stride) {
        ulonglong2 a0 = x8[i];
        ulonglong2 a1 = x8[i + stride];
        ulonglong2 a2 = x8[i + 2 * stride];
        ulonglong2 a3 = x8[i + 3 * stride];
        ulonglong2 b0 = d8[i];
        ulonglong2 b1 = d8[i + stride];
        ulonglong2 b2 = d8[i + 2 * stride];
        ulonglong2 b3 = d8[i + 3 * stride];
        u64 t;
        t = fma2(b0.x, neg1, a0.x); accA = fma2(t, t, accA);
        t = fma2(b0.y, neg1, a0.y); accB = fma2(t, t, accB);
        t = fma2(b1.x, neg1, a1.x); accA = fma2(t, t, accA);
        t = fma2(b1.y, neg1, a1.y); accB = fma2(t, t, accB);
        t = fma2(b2.x, neg1, a2.x); accA = fma2(t, t, accA);
        t = fma2(b2.y, neg1, a2.y); accB = fma2(t, t, accB);
        t = fma2(b3.x, neg1, a3.x); accA = fma2(t, t, accA);
        t = fma2(b3.y, neg1, a3.y); accB = fma2(t, t, accB);
    }
    for (; i < N4_A; i += stride) {
        ulonglong2 a = x8[i];
        ulonglong2 b = d8[i];
        u64 t;
        t = fma2(b.x, neg1, a.x); accA = fma2(t, t, accA);
        t = fma2(b.y, neg1, a.y); accB = fma2(t, t, accB);
    }

    __syncthreads();   // rs ready

    // ---- Part B: S2 = sum (encoded - latent @ rsrA^T)^2, f32x2 packed ----
    // One thread handles 4 consecutive e-columns of one batch row.
    const ulonglong2* __restrict__ enc8 = (const ulonglong2*)encoded;
    u64 s2p = 0ull;
    for (int idx = g; idx < N4_B; idx += stride) {
        int b  = idx >> 5;           // 32 float4 per row
        int e  = (idx & 31) << 2;    // base e column
        const float* __restrict__ lrow = latent + b * I_DIM;
        ulonglong2 ev = enc8[idx];
        u64 acc01 = mul2(ev.x, neg1);   // start at -enc
        u64 acc23 = mul2(ev.y, neg1);
        #pragma unroll
        for (int k = 0; k < I_DIM; k++) {
            float l = lrow[k];                     // warp-uniform broadcast
            u64 l2 = pack2(l, l);                  // ALU pipe
            const ulonglong2* r = (const ulonglong2*)&rs[k * E_DIM + e];
            ulonglong2 rv = *r;                    // LDS.128
            acc01 = fma2(l2, rv.x, acc01);
            acc23 = fma2(l2, rv.y, acc23);
        }
        s2p = fma2(acc01, acc01, s2p);
        s2p = fma2(acc23, acc23, s2p);
    }

    // ---- Block reduction (deterministic tree), partial = s1 + 1.1*s2 ----
    float2 fa = unpack2(accA);
    float2 fb = unpack2(accB);
    float2 fs = unpack2(s2p);
    float s1 = (fa.x + fa.y) + (fb.x + fb.y);
    float s2 = fs.x + fs.y;

    __shared__ float red[THREADS];
    red[tid] = s1 + 1.1f * s2;
    __syncthreads();
    #pragma unroll
    for (int off = THREADS / 2; off > 0; off >>= 1) {
        if (tid < off) red[tid] += red[tid + off];
        __syncthreads();
    }
    if (tid == 0) g_partials[blockIdx.x] = (double)red[0];
}

__global__ __launch_bounds__(512) void loss_final_kernel(
    const float* __restrict__ rsrA,
    float* __restrict__ out)
{
    __shared__ double sd[512];
    __shared__ float  sf[512];
    const int t = threadIdx.x;

    // Sum per-block partials (fixed order -> deterministic)
    double sum = 0.0;
    for (int j = t; j < NBLK; j += 512) sum += g_partials[j];
    sd[t] = sum;

    // S3: Gram residual, 400 (p,q) pairs, dot over E=128
    float s3 = 0.0f;
    if (t < I_DIM * I_DIM) {
        int p = t / I_DIM;
        int q = t - p * I_DIM;
        float gacc = 0.0f;
        #pragma unroll 8
        for (int e = 0; e < E_DIM; e++)
            gacc += rsrA[e * I_DIM + p] * rsrA[e * I_DIM + q];
        if (p == q) gacc -= 1.0f;
        s3 = gacc * gacc;
    }
    sf[t] = s3;
    __syncthreads();

    #pragma unroll
    for (int off = 256; off > 0; off >>= 1) {
        if (t < off) {
            sd[t] += sd[t + off];
            sf[t] += sf[t + off];
        }
        __syncthreads();
    }

    if (t == 0) {
        double total = sd[0] / (double)B_DIM
                     + 0.1 * (double)sf[0] / (double)(I_DIM * I_DIM);
        out[0] = (float)total;
    }
}

extern "C" void kernel_launch(void* const* d_in, const int* in_sizes, int n_in,
                              void* d_out, int out_size) {
    const float* x       = (const float*)d_in[0];
    const float* encoded = (const float*)d_in[1];
    const float* latent  = (const float*)d_in[2];
    const float* decoded = (const float*)d_in[3];
    const float* rsrA    = (const float*)d_in[4];
    float* out = (float*)d_out;

    loss_main_kernel<<<NBLK, THREADS>>>(x, encoded, latent, decoded, rsrA);
    loss_final_kernel<<<1, 512>>>(rsrA, out);
}

// round 9
// speedup vs baseline: 2.0964x; 1.7343x over previous
#include <cuda_runtime.h>

// LELoss: loss = S1/B + 1.1*S2/B + 0.1*S3/400
//   S1 = sum (x - decoded)^2              over [8192,1024]
//   S2 = sum (encoded - latent@rsrA^T)^2  over [8192,128], I=20
//   S3 = sum (rsrA^T rsrA - I)^2          over [20,20], E=128
// kNN/top_k in the reference is dead code (result unused).
//
// R6: single launch. Main body is the proven R1 codegen (best so far).
//  - Block 0 folds the tiny S3 Gram term into its partial (scaled 0.1*B/400).
//  - Last block (threadfence + wrapping atomicInc) just sums 592 floats.
// Epilogue is float-only and tiny -> no register pollution (R2/R4/R5 lesson).

#define B_DIM   8192
#define D_DIM   1024
#define E_DIM   128
#define I_DIM   20
#define THREADS 256
#define NBLK    592          // 4 waves of 148 SMs

#define N4_A    ((B_DIM * D_DIM) / 4)   // 2,097,152 float4 pairs
#define N4_B    ((B_DIM * E_DIM) / 4)   // 262,144 float4 of encoded

// 0.1 * B / (I*I): pre-scales S3 so epilogue only divides by B once
#define S3_SCALE (0.1f * (float)B_DIM / (float)(I_DIM * I_DIM))

__device__ float         g_partials[NBLK];
__device__ unsigned int  g_count = 0;   // atomicInc wraps to 0 -> replay-safe

__global__ __launch_bounds__(THREADS) void loss_fused_kernel(
    const float* __restrict__ x,
    const float* __restrict__ encoded,
    const float* __restrict__ latent,
    const float* __restrict__ decoded,
    const float* __restrict__ rsrA,
    float* __restrict__ out)
{
    __shared__ float rs[I_DIM * E_DIM];   // rsrA transposed: rs[i*128 + e]

    const int tid    = threadIdx.x;
    const int g      = blockIdx.x * THREADS + tid;
    const int stride = NBLK * THREADS;

    // Stage rsrA transposed into shared (10 KB)
    for (int j = tid; j < I_DIM * E_DIM; j += THREADS) {
        int i = j >> 7;          // j / 128
        int e = j & (E_DIM - 1); // j % 128
        rs[j] = rsrA[e * I_DIM + i];
    }

    // ---- Part A: S1 = sum (x - decoded)^2, float4, 4-way unrolled ----
    const float4* __restrict__ x4 = (const float4*)x;
    const float4* __restrict__ d4 = (const float4*)decoded;

    float s1 = 0.0f;
    int i = g;
    for (; i + 3 * stride < N4_A; i += 4 * stride) {
        float4 a0 = x4[i];
        float4 a1 = x4[i + stride];
        float4 a2 = x4[i + 2 * stride];
        float4 a3 = x4[i + 3 * stride];
        float4 b0 = d4[i];
        float4 b1 = d4[i + stride];
        float4 b2 = d4[i + 2 * stride];
        float4 b3 = d4[i + 3 * stride];
        float t;
        t = a0.x - b0.x; s1 += t * t;  t = a0.y - b0.y; s1 += t * t;
        t = a0.z - b0.z; s1 += t * t;  t = a0.w - b0.w; s1 += t * t;
        t = a1.x - b1.x; s1 += t * t;  t = a1.y - b1.y; s1 += t * t;
        t = a1.z - b1.z; s1 += t * t;  t = a1.w - b1.w; s1 += t * t;
        t = a2.x - b2.x; s1 += t * t;  t = a2.y - b2.y; s1 += t * t;
        t = a2.z - b2.z; s1 += t * t;  t = a2.w - b2.w; s1 += t * t;
        t = a3.x - b3.x; s1 += t * t;  t = a3.y - b3.y; s1 += t * t;
        t = a3.z - b3.z; s1 += t * t;  t = a3.w - b3.w; s1 += t * t;
    }
    for (; i < N4_A; i += stride) {
        float4 a = x4[i];
        float4 b = d4[i];
        float t;
        t = a.x - b.x; s1 += t * t;  t = a.y - b.y; s1 += t * t;
        t = a.z - b.z; s1 += t * t;  t = a.w - b.w; s1 += t * t;
    }

    __syncthreads();   // rs ready

    // ---- Part B: S2 = sum (encoded - latent @ rsrA^T)^2 ----
    const float4* __restrict__ enc4 = (const float4*)encoded;
    float s2 = 0.0f;
    for (int idx = g; idx < N4_B; idx += stride) {
        int b  = idx >> 5;           // 32 float4 per row
        int e  = (idx & 31) << 2;    // base e column
        const float* __restrict__ lrow = latent + b * I_DIM;
        float4 enc = enc4[idx];
        float a0 = -enc.x, a1 = -enc.y, a2 = -enc.z, a3 = -enc.w;
        #pragma unroll
        for (int k = 0; k < I_DIM; k++) {
            float l = lrow[k];                 // warp-broadcast, L1 hit
            const float* r = &rs[k * E_DIM + e];
            a0 += l * r[0];
            a1 += l * r[1];
            a2 += l * r[2];
            a3 += l * r[3];
        }
        s2 += a0 * a0 + a1 * a1 + a2 * a2 + a3 * a3;
    }

    float partial = s1 + 1.1f * s2;

    // ---- Block 0 only: S3 Gram residual, scaled, folded into partial ----
    // 400 (p,q) pairs over 256 threads; dot over E=128 from global rsrA
    // (coalesced 4B loads, whole matrix is 10 KB -> L1/L2 resident).
    if (blockIdx.x == 0) {
        float s3 = 0.0f;
        for (int pq = tid; pq < I_DIM * I_DIM; pq += THREADS) {
            int p = pq / I_DIM;
            int q = pq - p * I_DIM;
            float gacc = 0.0f;
            #pragma unroll 4
            for (int e = 0; e < E_DIM; e++)
                gacc += rsrA[e * I_DIM + p] * rsrA[e * I_DIM + q];
            if (p == q) gacc -= 1.0f;
            s3 += gacc * gacc;
        }
        partial += S3_SCALE * s3;
    }

    // ---- Block reduction (deterministic tree) ----
    __shared__ float red[THREADS];
    red[tid] = partial;
    __syncthreads();
    #pragma unroll
    for (int off = THREADS / 2; off > 0; off >>= 1) {
        if (tid < off) red[tid] += red[tid + off];
        __syncthreads();
    }

    // ---- Last-block epilogue: sum 592 floats, divide, store ----
    __shared__ bool is_last;
    if (tid == 0) {
        g_partials[blockIdx.x] = red[0];
        __threadfence();
        unsigned int prev = atomicInc(&g_count, NBLK - 1);  // wraps -> replay-safe
        is_last = (prev == NBLK - 1);
    }
    __syncthreads();

    if (is_last) {
        float sum = 0.0f;
        for (int j = tid; j < NBLK; j += THREADS)  // fixed order -> deterministic
            sum += g_partials[j];
        red[tid] = sum;
        __syncthreads();
        #pragma unroll
        for (int off = THREADS / 2; off > 0; off >>= 1) {
            if (tid < off) red[tid] += red[tid + off];
            __syncthreads();
        }
        if (tid == 0)
            out[0] = red[0] / (float)B_DIM;
    }
}

extern "C" void kernel_launch(void* const* d_in, const int* in_sizes, int n_in,
                              void* d_out, int out_size) {
    const float* x       = (const float*)d_in[0];
    const float* encoded = (const float*)d_in[1];
    const float* latent  = (const float*)d_in[2];
    const float* decoded = (const float*)d_in[3];
    const float* rsrA    = (const float*)d_in[4];
    float* out = (float*)d_out;

    loss_fused_kernel<<<NBLK, THREADS>>>(x, encoded, latent, decoded, rsrA, out);
}